// round 15
// baseline (speedup 1.0000x reference)
#include <cuda_runtime.h>
#include <cuda_fp16.h>
#include <cstdint>

// Problem dims (fixed per reference setup_inputs)
#define NTOK 16384   // B*T
#define DDIM 256
#define VDIM 8192
#define TVAL 2048

// Approx GEMM: only xh.eh (K=256). Exact fp32 rescore of top-4 candidates.
#define KPACK 256

// Argmin GEMM tiling — 4 warps/SMSP + fragment double-buffering
#define TM 128       // tokens per CTA (A resident in smem)
#define TN 128       // codes per N-tile
#define KCH 128      // K elems per streamed B chunk
#define NCHUNK 2     // K=256 / 128
#define NTILES (VDIM / TN)    // 64
#define TPB 512               // 16 warps: 4 (M) x 4 (N), warp tile 32x32

// Smem layout (bytes) — swizzled, pad-free rows
#define A_STRIDE 512          // 256 fp16 per row
#define B_STRIDE 256          // 128 fp16 per row
#define SM_A 0
#define SM_B (TM * A_STRIDE)                 // 65536
#define B_BUF (TN * B_STRIDE)                // 32768
#define SM_TOTAL (SM_B + 3 * B_BUF)          // 163840
// merge arrays overlay the (then-dead) B ring:
#define SM_REDV SM_B
#define SM_REDI (SM_B + TM * 16 * 4 * 4)     // +32768

#define SWZ8(off, r)  ((off) ^ (((r) & 7) << 4))
#define SWZ16(off, r) ((off) ^ (((r) & 15) << 4))

// Output layout (concatenated flattened, float32)
#define OFF_Q    0
#define OFF_CODE 4194304
#define OFF_NE   4210688
#define OFF_NCS  6307840
#define OFF_NEA  6316032

// ---------------------------------------------------------------------------
// Device scratch (no allocations allowed)
__device__ __half g_A[(size_t)NTOK * KPACK];   // xh
__device__ __half g_B[(size_t)VDIM * KPACK];   // eh
__device__ float g_sums[VDIM * DDIM];
__device__ float g_counts[VDIM];
__device__ float g_en2[VDIM];                  // exact 0.5*||e||^2 (fp32)
__device__ int   g_cand[NTOK * 4];             // approx top-4 per token

// ---------------------------------------------------------------------------
__device__ __forceinline__ uint32_t smem_u32(const void* p) {
    uint32_t a;
    asm("{ .reg .u64 t; cvta.to.shared.u64 t, %1; cvt.u32.u64 %0, t; }"
        : "=r"(a) : "l"(p));
    return a;
}
__device__ __forceinline__ void cp16(uint32_t dst, const void* src) {
    asm volatile("cp.async.cg.shared.global [%0], [%1], 16;"
                 :: "r"(dst), "l"(src) : "memory");
}
#define CP_COMMIT() asm volatile("cp.async.commit_group;" ::: "memory")
#define CP_WAIT(n)  asm volatile("cp.async.wait_group %0;" :: "n"(n) : "memory")

__device__ __forceinline__ void ldmx4(uint32_t (&r)[4], uint32_t addr) {
    asm volatile("ldmatrix.sync.aligned.m8n8.x4.shared.b16 {%0,%1,%2,%3}, [%4];"
                 : "=r"(r[0]), "=r"(r[1]), "=r"(r[2]), "=r"(r[3]) : "r"(addr));
}
__device__ __forceinline__ void mma16816(float (&d)[4], const uint32_t (&a)[4],
                                         uint32_t b0, uint32_t b1) {
    asm volatile(
        "mma.sync.aligned.m16n8k16.row.col.f32.f16.f16.f32 "
        "{%0,%1,%2,%3}, {%4,%5,%6,%7}, {%8,%9}, {%0,%1,%2,%3};"
        : "+f"(d[0]), "+f"(d[1]), "+f"(d[2]), "+f"(d[3])
        : "r"(a[0]), "r"(a[1]), "r"(a[2]), "r"(a[3]), "r"(b0), "r"(b1));
}

// strict-< top-4 insert (ascending-n scan => ties keep lower index)
__device__ __forceinline__ void top4_insert(float (&v)[4], int (&ix)[4],
                                            float s, int n) {
    if (s < v[3]) {
        if (s < v[1]) {
            v[3] = v[2]; ix[3] = ix[2];
            v[2] = v[1]; ix[2] = ix[1];
            if (s < v[0]) { v[1] = v[0]; ix[1] = ix[0]; v[0] = s; ix[0] = n; }
            else          { v[1] = s; ix[1] = n; }
        } else {
            if (s < v[2]) { v[3] = v[2]; ix[3] = ix[2]; v[2] = s; ix[2] = n; }
            else          { v[3] = s; ix[3] = n; }
        }
    }
}

// ---------------------------------------------------------------------------
// prep: xh only (vectorized: 4 elems/thread)
__global__ void prep_x_kernel(const float* __restrict__ x) {
    int i = blockIdx.x * blockDim.x + threadIdx.x;
    if (i >= (NTOK * DDIM) / 4) return;
    float4 v = ((const float4*)x)[i];
    __half2* dst = (__half2*)g_A;
    dst[2 * i]     = __floats2half2_rn(v.x, v.y);
    dst[2 * i + 1] = __floats2half2_rn(v.z, v.w);
}

// prep: eh + exact fp32 0.5*||e||^2 (one warp per codebook row)
__global__ void prep_e_kernel(const float* __restrict__ e) {
    int warp = (blockIdx.x * blockDim.x + threadIdx.x) >> 5;
    int lane = threadIdx.x & 31;
    if (warp >= VDIM) return;
    const float* row = e + (size_t)warp * DDIM;
    size_t base = (size_t)warp * KPACK;
    float s = 0.f;
#pragma unroll
    for (int j = 0; j < 8; j++) {
        int c = lane + 32 * j;
        float v = row[c];
        s += v * v;
        g_B[base + c] = __float2half(v);
    }
#pragma unroll
    for (int o = 16; o; o >>= 1) s += __shfl_xor_sync(0xffffffffu, s, o);
    if (lane == 0) g_en2[warp] = 0.5f * s;
}

__global__ void zero_kernel() {
    int i = blockIdx.x * blockDim.x + threadIdx.x;
    int stride = gridDim.x * blockDim.x;
    for (int idx = i; idx < VDIM * DDIM; idx += stride) g_sums[idx] = 0.f;
    for (int idx = i; idx < VDIM; idx += stride) g_counts[idx] = 0.f;
}

// ---------------------------------------------------------------------------
// Approx distance-GEMM (fp16 xh.eh) + min-filter top-4 + exact rescore later.
// 16 warps (4M x 4N, 32x32 tile): 4 warps/SMSP AND per-warp fragment
// double-buffering (next k16's LDSMs issue before this k16's HMMAs) so
// LDSM latency hides under MMA work. A resident; B via 3-stage ring.
__global__ __launch_bounds__(TPB, 1)
void argmin_mma_kernel() {
    extern __shared__ char smem[];
    const uint32_t sb = smem_u32(smem);
    const int tid  = threadIdx.x;
    const int lane = tid & 31;
    const int wid  = tid >> 5;
    const int tBase = blockIdx.x * TM;

    float* redv = (float*)(smem + SM_REDV);
    int*   redi = (int*)(smem + SM_REDI);

    const int warpM = wid & 3;
    const int warpN = wid >> 2;          // 0..3
    const int m0 = warpM * 32;
    const int n0 = warpN * 32;

    // ---- load resident A tile (128 x 256 fp16, SWZ16 rows) ----
#pragma unroll 4
    for (int i = 0; i < 8; i++) {
        int idx = tid + i * TPB;              // 4096 16B segments
        int r = idx >> 5, j = idx & 31;       // 32 segs per row
        cp16(sb + SM_A + r * A_STRIDE + SWZ16(j * 16, r),
             g_A + (size_t)(tBase + r) * KPACK + j * 8);
    }
    CP_COMMIT();

    // B chunk loader: 128 rows x 128 elems = 16 segs/row = 2048 segs, SWZ8
    auto loadB = [&](int buf, int vB, int boff) {
#pragma unroll
        for (int i = 0; i < 4; i++) {
            int idx = tid + i * TPB;
            int r = idx >> 4, j = idx & 15;
            cp16(sb + SM_B + buf * B_BUF + r * B_STRIDE + SWZ8(j * 16, r),
                 g_B + (size_t)(vB + r) * KPACK + boff + j * 8);
        }
        CP_COMMIT();
    };

    // prefetch chunks (0,0) and (0,1)
    loadB(0, 0, 0);
    loadB(1, 0, KCH);
    int pnt = 1, pkc = 0, pbuf = 2;   // next chunk to prefetch: (nt=1,kc=0)

    // per-lane addressing constants
    const uint32_t hi16 = (uint32_t)((lane >> 4) << 4);
    uint32_t aRow[2], bRow[2];
#pragma unroll
    for (int mb = 0; mb < 2; mb++)
        aRow[mb] = sb + SM_A + (m0 + mb * 16 + (lane & 15)) * A_STRIDE;
#pragma unroll
    for (int g = 0; g < 2; g++)
        bRow[g] = (uint32_t)((n0 + g * 16 + (lane & 15)) * B_STRIDE);

    // per-slot (4 token slots) approx top-4
    float tv[4][4];
    int   ti[4][4];
#pragma unroll
    for (int s = 0; s < 4; s++)
#pragma unroll
        for (int k = 0; k < 4; k++) { tv[s][k] = 3.4e38f; ti[s][k] = 0; }

    const int nCol = n0 + ((lane & 3) << 1);

    int cbuf = 0;
    for (int nt = 0; nt < NTILES; nt++) {
        const int vBase = nt * TN;

        float acc[2][4][4];
#pragma unroll
        for (int mb = 0; mb < 2; mb++)
#pragma unroll
            for (int nb = 0; nb < 4; nb++)
#pragma unroll
                for (int r = 0; r < 4; r++) acc[mb][nb][r] = 0.f;

        for (int kc = 0; kc < NCHUNK; kc++) {
            if (nt == NTILES - 1 && kc == NCHUNK - 1) { CP_WAIT(0); }
            else                                      { CP_WAIT(1); }
            __syncthreads();
            if (pnt < NTILES) {
                loadB(pbuf, pnt * TN, pkc * KCH);
                pbuf = (pbuf + 1) % 3;
                if (++pkc == NCHUNK) { pkc = 0; pnt++; }
            }

            const uint32_t aCol = (uint32_t)(kc * KCH * 2);   // bytes
            const uint32_t bBufBase = sb + SM_B + cbuf * B_BUF;
            cbuf = (cbuf + 1) % 3;

            // fragment double-buffer across the 8 k16 steps
            uint32_t a[2][2][4], b[2][2][4];
            {
                const uint32_t cA0 = SWZ16(aCol + hi16, lane);
                const uint32_t cB0 = SWZ8(hi16, lane);
#pragma unroll
                for (int mb = 0; mb < 2; mb++) ldmx4(a[0][mb], aRow[mb] + cA0);
#pragma unroll
                for (int g = 0; g < 2; g++)    ldmx4(b[0][g], bBufBase + bRow[g] + cB0);
            }
#pragma unroll
            for (int k16 = 0; k16 < 8; k16++) {
                const int cur = k16 & 1, nxt = cur ^ 1;
                if (k16 < 7) {
                    const uint32_t cA = SWZ16(aCol + (k16 + 1) * 32 + hi16, lane);
                    const uint32_t cB = SWZ8((uint32_t)((k16 + 1) * 32) + hi16, lane);
#pragma unroll
                    for (int mb = 0; mb < 2; mb++)
                        ldmx4(a[nxt][mb], aRow[mb] + cA);
#pragma unroll
                    for (int g = 0; g < 2; g++)
                        ldmx4(b[nxt][g], bBufBase + bRow[g] + cB);
                }
#pragma unroll
                for (int mb = 0; mb < 2; mb++)
#pragma unroll
                    for (int nb = 0; nb < 4; nb++) {
                        uint32_t b0 = (nb & 1) ? b[cur][nb >> 1][1] : b[cur][nb >> 1][0];
                        uint32_t b1 = (nb & 1) ? b[cur][nb >> 1][3] : b[cur][nb >> 1][2];
                        mma16816(acc[mb][nb], a[cur][mb], b0, b1);
                    }
            }
        }

        // ---- epilogue: branch-free min-pass, rare rescan+insert ----
        const float2* en2p = (const float2*)(g_en2 + vBase + nCol);
        float mmin[4];
#pragma unroll
        for (int s = 0; s < 4; s++) mmin[s] = 3.4e38f;
#pragma unroll
        for (int nb = 0; nb < 4; nb++) {
            float2 e2 = en2p[nb * 4];
#pragma unroll
            for (int mb = 0; mb < 2; mb++) {
                mmin[mb * 2 + 0] = fminf(mmin[mb * 2 + 0],
                    fminf(e2.x - acc[mb][nb][0], e2.y - acc[mb][nb][1]));
                mmin[mb * 2 + 1] = fminf(mmin[mb * 2 + 1],
                    fminf(e2.x - acc[mb][nb][2], e2.y - acc[mb][nb][3]));
            }
        }
#pragma unroll
        for (int s = 0; s < 4; s++) {
            if (mmin[s] < tv[s][3]) {      // rare path
                int mb = s >> 1, rb = (s & 1) << 1;
                for (int nb = 0; nb < 4; nb++) {
                    float2 e2 = en2p[nb * 4];
                    float s0 = e2.x - acc[mb][nb][rb];
                    float s1 = e2.y - acc[mb][nb][rb + 1];
                    int n = vBase + nCol + nb * 8;
                    top4_insert(tv[s], ti[s], s0, n);
                    top4_insert(tv[s], ti[s], s1, n + 1);
                }
            }
        }
    }

    // ---- merge: 16 sources x top-4 per token -> global top-4 ----
    __syncthreads();   // all mainloop smem traffic done before overlay
    {
        int src = (warpN << 2) | (lane & 3);   // 0..15
#pragma unroll
        for (int s = 0; s < 4; s++) {
            int row = m0 + ((s >> 1) << 4) + ((s & 1) << 3) + (lane >> 2);
            int base = (row * 16 + src) * 4;
#pragma unroll
            for (int k = 0; k < 4; k++) {
                redv[base + k] = tv[s][k];
                redi[base + k] = ti[s][k];
            }
        }
    }
    __syncthreads();
    if (tid < TM) {
        float bv[4]; int bi[4];
#pragma unroll
        for (int k = 0; k < 4; k++) { bv[k] = 3.4e38f; bi[k] = 0x7fffffff; }
        for (int e = 0; e < 64; e++) {
            float v = redv[tid * 64 + e];
            int   i = redi[tid * 64 + e];
            bool b3 = (v < bv[3]) || (v == bv[3] && i < bi[3]);
            if (b3) {
                bool b1 = (v < bv[1]) || (v == bv[1] && i < bi[1]);
                if (b1) {
                    bv[3] = bv[2]; bi[3] = bi[2];
                    bv[2] = bv[1]; bi[2] = bi[1];
                    bool b0 = (v < bv[0]) || (v == bv[0] && i < bi[0]);
                    if (b0) { bv[1] = bv[0]; bi[1] = bi[0]; bv[0] = v; bi[0] = i; }
                    else    { bv[1] = v; bi[1] = i; }
                } else {
                    bool b2 = (v < bv[2]) || (v == bv[2] && i < bi[2]);
                    if (b2) { bv[3] = bv[2]; bi[3] = bi[2]; bv[2] = v; bi[2] = i; }
                    else    { bv[3] = v; bi[3] = i; }
                }
            }
        }
#pragma unroll
        for (int k = 0; k < 4; k++)
            g_cand[(tBase + tid) * 4 + k] = bi[k];
    }
}

// ---------------------------------------------------------------------------
// Per-token: exact fp32 rescore of the 4 candidates, then quantize gather,
// codes, EMA scatter. Block = 256 threads = one token.
__global__ void scatter_kernel(const float* __restrict__ input,
                               const float* __restrict__ embed,
                               float* __restrict__ out) {
    __shared__ float ss[4];
    __shared__ int   scd[4];
    __shared__ int   sbest;
    int t = blockIdx.x;
    int tid = threadIdx.x, wid = tid >> 5, lane = tid & 31;

    if (wid < 4) {
        int c = g_cand[t * 4 + wid];
        const float* xr = input + (size_t)t * DDIM;
        const float* er = embed + (size_t)c * DDIM;
        float dot = 0.f;
#pragma unroll
        for (int j = 0; j < 8; j++)
            dot += xr[lane + 32 * j] * er[lane + 32 * j];
#pragma unroll
        for (int o = 16; o; o >>= 1) dot += __shfl_xor_sync(0xffffffffu, dot, o);
        if (lane == 0) { ss[wid] = g_en2[c] - dot; scd[wid] = c; }
    }
    __syncthreads();
    if (tid == 0) {
        float bv = ss[0]; int bi = scd[0];
#pragma unroll
        for (int k = 1; k < 4; k++)
            if (ss[k] < bv || (ss[k] == bv && scd[k] < bi)) { bv = ss[k]; bi = scd[k]; }
        sbest = bi;
        out[OFF_CODE + t] = (float)bi;
    }
    __syncthreads();
    int c = sbest, d = tid;
    out[OFF_Q + (size_t)t * DDIM + d] = embed[(size_t)c * DDIM + d];
    atomicAdd(&g_sums[(size_t)c * DDIM + d], input[(size_t)t * DDIM + d]);
    if (d == 0) atomicAdd(&g_counts[c], 1.0f);
}

__global__ void finalize_kernel(const float* __restrict__ cluster_size,
                                const float* __restrict__ embed_avg,
                                float* __restrict__ out) {
    int idx = blockIdx.x * blockDim.x + threadIdx.x;
    if (idx >= VDIM * DDIM) return;
    int v = idx >> 8;
    float ncs = cluster_size[v] * 0.99f + g_counts[v] * 0.01f;
    float avg = embed_avg[idx] * 0.99f + (g_sums[idx] * (1.0f / TVAL)) * 0.01f;
    out[OFF_NEA + idx] = avg;
    out[OFF_NE + idx]  = avg / (ncs + 1e-5f);
    if ((idx & 255) == 0) out[OFF_NCS + v] = ncs;
}

// ---------------------------------------------------------------------------
extern "C" void kernel_launch(void* const* d_in, const int* in_sizes, int n_in,
                              void* d_out, int out_size) {
    const float* input        = (const float*)d_in[0];
    const float* embed        = (const float*)d_in[1];
    const float* cluster_size = (const float*)d_in[2];
    const float* embed_avg    = (const float*)d_in[3];
    float* out = (float*)d_out;

    cudaFuncSetAttribute(argmin_mma_kernel,
                         cudaFuncAttributeMaxDynamicSharedMemorySize, SM_TOTAL);

    // argmin is the 4th launch so ncu's fixed-skip capture profiles it
    prep_x_kernel<<<(NTOK * DDIM / 4) / 256, 256>>>(input);
    prep_e_kernel<<<VDIM / 8, 256>>>(embed);
    zero_kernel<<<2048, 256>>>();
    argmin_mma_kernel<<<NTOK / TM, TPB, SM_TOTAL>>>();
    scatter_kernel<<<NTOK, DDIM>>>(input, embed, out);
    finalize_kernel<<<(VDIM * DDIM + 255) / 256, 256>>>(cluster_size, embed_avg, out);
}

// round 16
// speedup vs baseline: 1.5681x; 1.5681x over previous
#include <cuda_runtime.h>
#include <cuda_fp16.h>
#include <cstdint>

// Problem dims (fixed per reference setup_inputs)
#define NTOK 16384   // B*T
#define DDIM 256
#define VDIM 8192
#define TVAL 2048

// Approx GEMM: only xh.eh (K=256). Exact fp32 rescore of top-4 candidates.
#define KPACK 256

// Argmin GEMM tiling — 2 CTAs/SM for cross-CTA latency hiding
#define TM 64        // tokens per CTA (A resident in smem)
#define TN 128       // codes per N-tile
#define KCH 64       // K elems per streamed B chunk
#define NCHUNK 4     // K=256 / 64
#define NTILES (VDIM / TN)    // 64
#define TPB 256               // 8 warps: 2 (M) x 4 (N), warp tile 32x32

// Smem layout (bytes) — swizzled, pad-free rows
#define A_STRIDE 512          // 256 fp16 per row
#define B_STRIDE 128          // 64 fp16 per row
#define SM_A 0
#define SM_B (TM * A_STRIDE)                 // 32768
#define B_BUF (TN * B_STRIDE)                // 16384
#define SM_TOTAL (SM_B + 3 * B_BUF)          // 81920  (x2 CTAs = 163840 OK)
// merge arrays overlay the (then-dead) B ring:
#define SM_REDV SM_B
#define SM_REDI (SM_B + TM * 16 * 4 * 4)     // +16384

#define SWZ8(off, r)  ((off) ^ (((r) & 7) << 4))
#define SWZ16(off, r) ((off) ^ (((r) & 15) << 4))

// Output layout (concatenated flattened, float32)
#define OFF_Q    0
#define OFF_CODE 4194304
#define OFF_NE   4210688
#define OFF_NCS  6307840
#define OFF_NEA  6316032

// ---------------------------------------------------------------------------
// Device scratch (no allocations allowed)
__device__ __half g_A[(size_t)NTOK * KPACK];   // xh
__device__ __half g_B[(size_t)VDIM * KPACK];   // eh
__device__ float g_sums[VDIM * DDIM];
__device__ float g_counts[VDIM];
__device__ float g_en2[VDIM];                  // exact 0.5*||e||^2 (fp32)
__device__ int   g_cand[NTOK * 4];             // approx top-4 per token

// ---------------------------------------------------------------------------
__device__ __forceinline__ uint32_t smem_u32(const void* p) {
    uint32_t a;
    asm("{ .reg .u64 t; cvta.to.shared.u64 t, %1; cvt.u32.u64 %0, t; }"
        : "=r"(a) : "l"(p));
    return a;
}
__device__ __forceinline__ void cp16(uint32_t dst, const void* src) {
    asm volatile("cp.async.cg.shared.global [%0], [%1], 16;"
                 :: "r"(dst), "l"(src) : "memory");
}
#define CP_COMMIT() asm volatile("cp.async.commit_group;" ::: "memory")
#define CP_WAIT(n)  asm volatile("cp.async.wait_group %0;" :: "n"(n) : "memory")

__device__ __forceinline__ void ldmx4(uint32_t (&r)[4], uint32_t addr) {
    asm volatile("ldmatrix.sync.aligned.m8n8.x4.shared.b16 {%0,%1,%2,%3}, [%4];"
                 : "=r"(r[0]), "=r"(r[1]), "=r"(r[2]), "=r"(r[3]) : "r"(addr));
}
__device__ __forceinline__ void mma16816(float (&d)[4], const uint32_t (&a)[4],
                                         uint32_t b0, uint32_t b1) {
    asm volatile(
        "mma.sync.aligned.m16n8k16.row.col.f32.f16.f16.f32 "
        "{%0,%1,%2,%3}, {%4,%5,%6,%7}, {%8,%9}, {%0,%1,%2,%3};"
        : "+f"(d[0]), "+f"(d[1]), "+f"(d[2]), "+f"(d[3])
        : "r"(a[0]), "r"(a[1]), "r"(a[2]), "r"(a[3]), "r"(b0), "r"(b1));
}

// strict-< top-4 insert (ascending-n scan => ties keep lower index)
__device__ __forceinline__ void top4_insert(float (&v)[4], int (&ix)[4],
                                            float s, int n) {
    if (s < v[3]) {
        if (s < v[1]) {
            v[3] = v[2]; ix[3] = ix[2];
            v[2] = v[1]; ix[2] = ix[1];
            if (s < v[0]) { v[1] = v[0]; ix[1] = ix[0]; v[0] = s; ix[0] = n; }
            else          { v[1] = s; ix[1] = n; }
        } else {
            if (s < v[2]) { v[3] = v[2]; ix[3] = ix[2]; v[2] = s; ix[2] = n; }
            else          { v[3] = s; ix[3] = n; }
        }
    }
}

// ---------------------------------------------------------------------------
// prep: xh only (vectorized: 4 elems/thread)
__global__ void prep_x_kernel(const float* __restrict__ x) {
    int i = blockIdx.x * blockDim.x + threadIdx.x;
    if (i >= (NTOK * DDIM) / 4) return;
    float4 v = ((const float4*)x)[i];
    __half2* dst = (__half2*)g_A;
    dst[2 * i]     = __floats2half2_rn(v.x, v.y);
    dst[2 * i + 1] = __floats2half2_rn(v.z, v.w);
}

// prep: eh + exact fp32 0.5*||e||^2 (one warp per codebook row)
__global__ void prep_e_kernel(const float* __restrict__ e) {
    int warp = (blockIdx.x * blockDim.x + threadIdx.x) >> 5;
    int lane = threadIdx.x & 31;
    if (warp >= VDIM) return;
    const float* row = e + (size_t)warp * DDIM;
    size_t base = (size_t)warp * KPACK;
    float s = 0.f;
#pragma unroll
    for (int j = 0; j < 8; j++) {
        int c = lane + 32 * j;
        float v = row[c];
        s += v * v;
        g_B[base + c] = __float2half(v);
    }
#pragma unroll
    for (int o = 16; o; o >>= 1) s += __shfl_xor_sync(0xffffffffu, s, o);
    if (lane == 0) g_en2[warp] = 0.5f * s;
}

__global__ void zero_kernel() {
    int i = blockIdx.x * blockDim.x + threadIdx.x;
    int stride = gridDim.x * blockDim.x;
    for (int idx = i; idx < VDIM * DDIM; idx += stride) g_sums[idx] = 0.f;
    for (int idx = i; idx < VDIM; idx += stride) g_counts[idx] = 0.f;
}

// ---------------------------------------------------------------------------
// Approx distance-GEMM (fp16 xh.eh) + min-filter top-4 + exact rescore later.
// 2 CTAs/SM (TM=64, 80KB smem each): independent barrier domains overlap —
// one CTA's epilogue/barrier/LDSM-refill hides under the other's HMMAs.
// 8 warps (2M x 4N, 32x32 tile), ~105 regs (no spills at cap 128).
__global__ __launch_bounds__(TPB, 2)
void argmin_mma_kernel() {
    extern __shared__ char smem[];
    const uint32_t sb = smem_u32(smem);
    const int tid  = threadIdx.x;
    const int lane = tid & 31;
    const int wid  = tid >> 5;
    const int tBase = blockIdx.x * TM;

    float* redv = (float*)(smem + SM_REDV);
    int*   redi = (int*)(smem + SM_REDI);

    const int warpM = wid & 1;
    const int warpN = wid >> 1;          // 0..3
    const int m0 = warpM * 32;
    const int n0 = warpN * 32;

    // ---- load resident A tile (64 x 256 fp16, SWZ16 rows) ----
#pragma unroll 4
    for (int i = 0; i < 8; i++) {
        int idx = tid + i * TPB;              // 2048 16B segments
        int r = idx >> 5, j = idx & 31;       // 32 segs per row
        cp16(sb + SM_A + r * A_STRIDE + SWZ16(j * 16, r),
             g_A + (size_t)(tBase + r) * KPACK + j * 8);
    }
    CP_COMMIT();

    // B chunk loader: 128 rows x 64 elems = 8 segs/row = 1024 segs, SWZ8
    auto loadB = [&](int buf, int vB, int boff) {
#pragma unroll
        for (int i = 0; i < 4; i++) {
            int idx = tid + i * TPB;
            int r = idx >> 3, j = idx & 7;
            cp16(sb + SM_B + buf * B_BUF + r * B_STRIDE + SWZ8(j * 16, r),
                 g_B + (size_t)(vB + r) * KPACK + boff + j * 8);
        }
        CP_COMMIT();
    };

    // prefetch chunks (0,0) and (0,1)
    loadB(0, 0, 0);
    loadB(1, 0, KCH);
    int pnt = 0, pkc = 2, pbuf = 2;   // next chunk to prefetch

    // per-lane addressing constants
    const uint32_t hi16 = (uint32_t)((lane >> 4) << 4);
    uint32_t aRow[2], bRow[2];
#pragma unroll
    for (int mb = 0; mb < 2; mb++)
        aRow[mb] = sb + SM_A + (m0 + mb * 16 + (lane & 15)) * A_STRIDE;
#pragma unroll
    for (int g = 0; g < 2; g++)
        bRow[g] = (uint32_t)((n0 + g * 16 + (lane & 15)) * B_STRIDE);

    // per-slot (4 token slots) approx top-4
    float tv[4][4];
    int   ti[4][4];
#pragma unroll
    for (int s = 0; s < 4; s++)
#pragma unroll
        for (int k = 0; k < 4; k++) { tv[s][k] = 3.4e38f; ti[s][k] = 0; }

    const int nCol = n0 + ((lane & 3) << 1);

    int cbuf = 0;
    for (int nt = 0; nt < NTILES; nt++) {
        const int vBase = nt * TN;

        float acc[2][4][4];
#pragma unroll
        for (int mb = 0; mb < 2; mb++)
#pragma unroll
            for (int nb = 0; nb < 4; nb++)
#pragma unroll
                for (int r = 0; r < 4; r++) acc[mb][nb][r] = 0.f;

        for (int kc = 0; kc < NCHUNK; kc++) {
            if (nt == NTILES - 1 && kc == NCHUNK - 1) { CP_WAIT(0); }
            else                                      { CP_WAIT(1); }
            __syncthreads();
            if (pnt < NTILES) {
                loadB(pbuf, pnt * TN, pkc * KCH);
                pbuf = (pbuf + 1) % 3;
                if (++pkc == NCHUNK) { pkc = 0; pnt++; }
            }

            const uint32_t aCol = (uint32_t)(kc * KCH * 2);   // bytes
            const uint32_t bBufBase = sb + SM_B + cbuf * B_BUF;
            cbuf = (cbuf + 1) % 3;

#pragma unroll
            for (int k16 = 0; k16 < 4; k16++) {
                const uint32_t cA = SWZ16(aCol + k16 * 32 + hi16, lane);
                const uint32_t cB = SWZ8((uint32_t)(k16 * 32) + hi16, lane);
                uint32_t a[2][4], b[2][4];
#pragma unroll
                for (int mb = 0; mb < 2; mb++)
                    ldmx4(a[mb], aRow[mb] + cA);
#pragma unroll
                for (int g = 0; g < 2; g++)
                    ldmx4(b[g], bBufBase + bRow[g] + cB);
#pragma unroll
                for (int mb = 0; mb < 2; mb++)
#pragma unroll
                    for (int nb = 0; nb < 4; nb++) {
                        uint32_t b0 = (nb & 1) ? b[nb >> 1][1] : b[nb >> 1][0];
                        uint32_t b1 = (nb & 1) ? b[nb >> 1][3] : b[nb >> 1][2];
                        mma16816(acc[mb][nb], a[mb], b0, b1);
                    }
            }
        }

        // ---- epilogue: branch-free min-pass, rare rescan+insert ----
        const float2* en2p = (const float2*)(g_en2 + vBase + nCol);
        float mmin[4];
#pragma unroll
        for (int s = 0; s < 4; s++) mmin[s] = 3.4e38f;
#pragma unroll
        for (int nb = 0; nb < 4; nb++) {
            float2 e2 = en2p[nb * 4];
#pragma unroll
            for (int mb = 0; mb < 2; mb++) {
                mmin[mb * 2 + 0] = fminf(mmin[mb * 2 + 0],
                    fminf(e2.x - acc[mb][nb][0], e2.y - acc[mb][nb][1]));
                mmin[mb * 2 + 1] = fminf(mmin[mb * 2 + 1],
                    fminf(e2.x - acc[mb][nb][2], e2.y - acc[mb][nb][3]));
            }
        }
#pragma unroll
        for (int s = 0; s < 4; s++) {
            if (mmin[s] < tv[s][3]) {      // rare path
                int mb = s >> 1, rb = (s & 1) << 1;
                for (int nb = 0; nb < 4; nb++) {
                    float2 e2 = en2p[nb * 4];
                    float s0 = e2.x - acc[mb][nb][rb];
                    float s1 = e2.y - acc[mb][nb][rb + 1];
                    int n = vBase + nCol + nb * 8;
                    top4_insert(tv[s], ti[s], s0, n);
                    top4_insert(tv[s], ti[s], s1, n + 1);
                }
            }
        }
        // no barrier needed: epilogue touches no smem; B-ring hazard covered
        // by CP_WAIT+__syncthreads at the next chunk.
    }

    // ---- merge: 16 sources x top-4 per token -> global top-4 ----
    __syncthreads();   // all mainloop smem traffic done before overlay
    {
        int src = (warpN << 2) | (lane & 3);   // 0..15
#pragma unroll
        for (int s = 0; s < 4; s++) {
            int row = m0 + ((s >> 1) << 4) + ((s & 1) << 3) + (lane >> 2);
            int base = (row * 16 + src) * 4;
#pragma unroll
            for (int k = 0; k < 4; k++) {
                redv[base + k] = tv[s][k];
                redi[base + k] = ti[s][k];
            }
        }
    }
    __syncthreads();
    if (tid < TM) {
        float bv[4]; int bi[4];
#pragma unroll
        for (int k = 0; k < 4; k++) { bv[k] = 3.4e38f; bi[k] = 0x7fffffff; }
        for (int e = 0; e < 64; e++) {
            float v = redv[tid * 64 + e];
            int   i = redi[tid * 64 + e];
            bool b3 = (v < bv[3]) || (v == bv[3] && i < bi[3]);
            if (b3) {
                bool b1 = (v < bv[1]) || (v == bv[1] && i < bi[1]);
                if (b1) {
                    bv[3] = bv[2]; bi[3] = bi[2];
                    bv[2] = bv[1]; bi[2] = bi[1];
                    bool b0 = (v < bv[0]) || (v == bv[0] && i < bi[0]);
                    if (b0) { bv[1] = bv[0]; bi[1] = bi[0]; bv[0] = v; bi[0] = i; }
                    else    { bv[1] = v; bi[1] = i; }
                } else {
                    bool b2 = (v < bv[2]) || (v == bv[2] && i < bi[2]);
                    if (b2) { bv[3] = bv[2]; bi[3] = bi[2]; bv[2] = v; bi[2] = i; }
                    else    { bv[3] = v; bi[3] = i; }
                }
            }
        }
#pragma unroll
        for (int k = 0; k < 4; k++)
            g_cand[(tBase + tid) * 4 + k] = bi[k];
    }
}

// ---------------------------------------------------------------------------
// Per-token: exact fp32 rescore of the 4 candidates, then quantize gather,
// codes, EMA scatter. Block = 256 threads = one token.
__global__ void scatter_kernel(const float* __restrict__ input,
                               const float* __restrict__ embed,
                               float* __restrict__ out) {
    __shared__ float ss[4];
    __shared__ int   scd[4];
    __shared__ int   sbest;
    int t = blockIdx.x;
    int tid = threadIdx.x, wid = tid >> 5, lane = tid & 31;

    if (wid < 4) {
        int c = g_cand[t * 4 + wid];
        const float* xr = input + (size_t)t * DDIM;
        const float* er = embed + (size_t)c * DDIM;
        float dot = 0.f;
#pragma unroll
        for (int j = 0; j < 8; j++)
            dot += xr[lane + 32 * j] * er[lane + 32 * j];
#pragma unroll
        for (int o = 16; o; o >>= 1) dot += __shfl_xor_sync(0xffffffffu, dot, o);
        if (lane == 0) { ss[wid] = g_en2[c] - dot; scd[wid] = c; }
    }
    __syncthreads();
    if (tid == 0) {
        float bv = ss[0]; int bi = scd[0];
#pragma unroll
        for (int k = 1; k < 4; k++)
            if (ss[k] < bv || (ss[k] == bv && scd[k] < bi)) { bv = ss[k]; bi = scd[k]; }
        sbest = bi;
        out[OFF_CODE + t] = (float)bi;
    }
    __syncthreads();
    int c = sbest, d = tid;
    out[OFF_Q + (size_t)t * DDIM + d] = embed[(size_t)c * DDIM + d];
    atomicAdd(&g_sums[(size_t)c * DDIM + d], input[(size_t)t * DDIM + d]);
    if (d == 0) atomicAdd(&g_counts[c], 1.0f);
}

__global__ void finalize_kernel(const float* __restrict__ cluster_size,
                                const float* __restrict__ embed_avg,
                                float* __restrict__ out) {
    int idx = blockIdx.x * blockDim.x + threadIdx.x;
    if (idx >= VDIM * DDIM) return;
    int v = idx >> 8;
    float ncs = cluster_size[v] * 0.99f + g_counts[v] * 0.01f;
    float avg = embed_avg[idx] * 0.99f + (g_sums[idx] * (1.0f / TVAL)) * 0.01f;
    out[OFF_NEA + idx] = avg;
    out[OFF_NE + idx]  = avg / (ncs + 1e-5f);
    if ((idx & 255) == 0) out[OFF_NCS + v] = ncs;
}

// ---------------------------------------------------------------------------
extern "C" void kernel_launch(void* const* d_in, const int* in_sizes, int n_in,
                              void* d_out, int out_size) {
    const float* input        = (const float*)d_in[0];
    const float* embed        = (const float*)d_in[1];
    const float* cluster_size = (const float*)d_in[2];
    const float* embed_avg    = (const float*)d_in[3];
    float* out = (float*)d_out;

    cudaFuncSetAttribute(argmin_mma_kernel,
                         cudaFuncAttributeMaxDynamicSharedMemorySize, SM_TOTAL);

    // argmin is the 4th launch so ncu's fixed-skip capture profiles it
    prep_x_kernel<<<(NTOK * DDIM / 4) / 256, 256>>>(input);
    prep_e_kernel<<<VDIM / 8, 256>>>(embed);
    zero_kernel<<<2048, 256>>>();
    argmin_mma_kernel<<<NTOK / TM, TPB, SM_TOTAL>>>();
    scatter_kernel<<<NTOK, DDIM>>>(input, embed, out);
    finalize_kernel<<<(VDIM * DDIM + 255) / 256, 256>>>(cluster_size, embed_avg, out);
}